// round 9
// baseline (speedup 1.0000x reference)
#include <cuda_runtime.h>

#define Bn   256
#define Tn   512
#define Dn   64
#define En   128
#define H1n  128
#define H2n  64
#define Vn   10000
#define ML   30
#define SOS_ 1
#define EOS_ 2

typedef unsigned long long ull;

// ---------------- persistent state + prepped weights (device globals) -------
__device__ float g_h1[2][Bn * H1n];        // ping-pong
__device__ float g_c1[Bn * H1n];
__device__ float g_h2[2][Bn * H2n];        // ping-pong
__device__ float g_c2[Bn * H2n];
__device__ float g_x[Bn * 128];            // [h2(64) | ctx(64)] pred input
__device__ ull   g_amax[Bn];               // packed (fkey(val)<<32 | ~v)

// k-major, gate-interleaved (col = 4*hdim + gate, gates i,f,g,o)
__device__ float g_w1R[320 * 512];         // k<192: wih1, k>=192: whh1
__device__ float g_w2R[192 * 256];         // k<128: wih2, k>=128: whh2
__device__ float g_b1R[512];
__device__ float g_b2R[256];
__device__ float g_wqT[64 * 64];           // [k][d]
__device__ float g_wpT[128 * Vn];          // [k][v]

__device__ __forceinline__ unsigned int fkey(float f) {
    unsigned int u = __float_as_uint(f);
    return (u & 0x80000000u) ? ~u : (u | 0x80000000u);
}
__device__ __forceinline__ float sigm(float x) { return 1.0f / (1.0f + expf(-x)); }

__device__ __forceinline__ void fma2(ull& d, ull a, ull b) {
    asm("fma.rn.f32x2 %0, %1, %2, %0;" : "+l"(d) : "l"(a), "l"(b));
}
__device__ __forceinline__ ull dup2(float x) {
    unsigned int u = __float_as_uint(x); ull r;
    asm("mov.b64 %0, {%1, %1};" : "=l"(r) : "r"(u));
    return r;
}
__device__ __forceinline__ void unpk2(ull a, float& lo, float& hi) {
    unsigned int ul, uh;
    asm("mov.b64 {%0, %1}, %2;" : "=r"(ul), "=r"(uh) : "l"(a));
    lo = __uint_as_float(ul); hi = __uint_as_float(uh);
}
__device__ __forceinline__ void cpa16(void* s, const void* g) {
    unsigned sa = (unsigned)__cvta_generic_to_shared(s);
    asm volatile("cp.async.cg.shared.global [%0], [%1], 16;" :: "r"(sa), "l"(g));
}
#define CP_COMMIT()  asm volatile("cp.async.commit_group;")
#define CP_WAIT(n)   asm volatile("cp.async.wait_group %0;" :: "n"(n))
__device__ __forceinline__ void cp_wait_dyn(int n) {
    switch (n) {
    case 0: CP_WAIT(0); break;
    case 1: CP_WAIT(1); break;
    case 2: CP_WAIT(2); break;
    case 3: CP_WAIT(3); break;
    case 4: CP_WAIT(4); break;
    case 5: CP_WAIT(5); break;
    case 6: CP_WAIT(6); break;
    default: CP_WAIT(7); break;
    }
}

// ---------------- one-time prep ---------------------------------------------
__global__ void k_prep_small(const float* __restrict__ wih1, const float* __restrict__ whh1,
                             const float* __restrict__ bih1, const float* __restrict__ bhh1,
                             const float* __restrict__ wih2, const float* __restrict__ whh2,
                             const float* __restrict__ bih2, const float* __restrict__ bhh2,
                             const float* __restrict__ wq) {
    int n = blockDim.x * gridDim.x;
    int t0 = blockIdx.x * blockDim.x + threadIdx.x;
    for (int i = t0; i < 320 * 512; i += n) {
        int k = i >> 9, c = i & 511;
        int h = c >> 2, g = c & 3, r = g * 128 + h;
        g_w1R[i] = (k < 192) ? wih1[r * 192 + k] : whh1[r * 128 + (k - 192)];
    }
    for (int i = t0; i < 192 * 256; i += n) {
        int k = i >> 8, c = i & 255;
        int h = c >> 2, g = c & 3, r = g * 64 + h;
        g_w2R[i] = (k < 128) ? wih2[r * 128 + k] : whh2[r * 64 + (k - 128)];
    }
    for (int i = t0; i < 64 * 64; i += n) {
        int k = i >> 6, d = i & 63;
        g_wqT[i] = wq[d * 64 + k];
    }
    for (int c = t0; c < 512; c += n) {
        int h = c >> 2, g = c & 3, r = g * 128 + h;
        g_b1R[c] = bih1[r] + bhh1[r];
    }
    for (int c = t0; c < 256; c += n) {
        int h = c >> 2, g = c & 3, r = g * 64 + h;
        g_b2R[c] = bih2[r] + bhh2[r];
    }
}

// tiled transpose wp[10000][128] -> wpT[128][10000]
__global__ void k_prep_wp(const float* __restrict__ wp) {
    __shared__ float t[32][33];
    int vt = blockIdx.x * 32, kt = blockIdx.y * 32;
    int tx = threadIdx.x & 31, ty = threadIdx.x >> 5;   // 32 x 8
    #pragma unroll
    for (int i = 0; i < 4; i++) {
        int v = vt + ty + i * 8;
        if (v < Vn) t[ty + i * 8][tx] = wp[(size_t)v * 128 + kt + tx];
    }
    __syncthreads();
    int v = vt + tx;
    if (v < Vn) {
        #pragma unroll
        for (int i = 0; i < 4; i++) {
            int k = kt + ty + i * 8;
            g_wpT[(size_t)k * Vn + v] = t[tx][ty + i * 8];
        }
    }
}

__global__ void k_init() {
    int i = blockIdx.x * blockDim.x + threadIdx.x;
    if (i < Bn * H1n) { g_h1[0][i] = 0.f; g_h1[1][i] = 0.f; g_c1[i] = 0.f; }
    if (i < Bn * H2n) { g_h2[0][i] = 0.f; g_h2[1][i] = 0.f; g_c2[i] = 0.f; }
    if (i < Bn * 128) g_x[i] = 0.f;
    if (i < Bn) g_amax[i] = (ull)(~(unsigned int)SOS_);
}

// ---------------- k_lstm1: grid (8 rowtiles, 16 btiles), 256 thr ------------
// 64 rows' (16 hdims) x 16 b, k=320 in 5 chunks of 64 — ALL staged upfront.
#define L1_NC    5
#define L1_SW    0                                  // [5][64][64] f = 81920
#define L1_SXD   81920                              // [320][16] ull = 40960
#define L1_SG    (81920 + 40960)                    // [64][18] f    = 4608
#define L1_TOK   (L1_SG + 4608)
#define L1_SMEM  (L1_TOK + 64)

__global__ void __launch_bounds__(256) k_lstm1(const float* __restrict__ emb, int p) {
    extern __shared__ __align__(16) char sm[];
    float (*s_w)[64][64] = (float(*)[64][64])(sm + L1_SW);   // [5 chunks]
    ull   (*s_xd)[16]    = (ull(*)[16])(sm + L1_SXD);
    float (*s_g)[18]     = (float(*)[18])(sm + L1_SG);
    int*  s_tok          = (int*)(sm + L1_TOK);

    const int tid = threadIdx.x;
    const int rt = blockIdx.x, bt = blockIdx.y;
    const int r0 = rt * 64, b0 = bt * 16;
    const float* __restrict__ h1old = g_h1[p];
    float* __restrict__ h1new = g_h1[p ^ 1];

    // stage ALL weight chunks now (one commit group per chunk)
    #pragma unroll
    for (int c = 0; c < L1_NC; c++) {
        #pragma unroll
        for (int i = 0; i < 4; i++) {
            int idx = tid + i * 256;
            int kr = idx >> 4, j4 = idx & 15;
            cpa16(&s_w[c][kr][j4 * 4],
                  &g_w1R[(size_t)(c * 64 + kr) * 512 + r0 + j4 * 4]);
        }
        CP_COMMIT();
    }

    if (tid < 16) {
        ull a = g_amax[b0 + tid];
        s_tok[tid] = (int)(~(unsigned int)(a & 0xFFFFFFFFull));
    }
    __syncthreads();

    // x fill: 320 k x 16 b, stored as dup'd f32x2 pairs (overlaps staging)
    for (int idx = tid; idx < 320 * 16; idx += 256) {
        int k = idx >> 4, b = idx & 15;
        float v;
        if (k < 128) {
            int t = s_tok[b];
            v = (t == EOS_) ? 0.f : emb[(size_t)t * En + k];
        } else if (k < 192) {
            v = g_x[(b0 + b) * 128 + 64 + (k - 128)];
        } else {
            v = h1old[(b0 + b) * H1n + (k - 192)];
        }
        s_xd[k][b] = dup2(v);
    }

    const int RP = tid >> 3, Bg = tid & 7;   // rows (2RP,2RP+1) x b (2Bg,2Bg+1)
    ull a0 = 0, a1 = 0;

    #pragma unroll 1
    for (int c = 0; c < L1_NC; c++) {
        cp_wait_dyn(L1_NC - 1 - c);
        __syncthreads();
        const float* wb = &s_w[c][0][0];
        const ull*   xb = &s_xd[c * 64][0];
        #pragma unroll
        for (int kk = 0; kk < 64; kk++) {
            ull w = *(const ull*)(wb + kk * 64 + 2 * RP);
            ulonglong2 x2 = *(const ulonglong2*)(xb + kk * 16 + 2 * Bg);
            fma2(a0, w, x2.x);
            fma2(a1, w, x2.y);
        }
    }
    __syncthreads();

    // gates -> smem with bias (a0: b=2Bg, a1: b=2Bg+1; pair = rows 2RP,2RP+1)
    {
        float bl = g_b1R[r0 + 2 * RP], bh = g_b1R[r0 + 2 * RP + 1];
        float v0, v1;
        unpk2(a0, v0, v1);
        s_g[2 * RP][2 * Bg] = v0 + bl; s_g[2 * RP + 1][2 * Bg] = v1 + bh;
        unpk2(a1, v0, v1);
        s_g[2 * RP][2 * Bg + 1] = v0 + bl; s_g[2 * RP + 1][2 * Bg + 1] = v1 + bh;
    }
    __syncthreads();

    // cell update: 16 hdims x 16 b
    {
        int b = tid & 15, hl = tid >> 4;
        float gi = s_g[4 * hl][b],     gf = s_g[4 * hl + 1][b];
        float gg = s_g[4 * hl + 2][b], go = s_g[4 * hl + 3][b];
        int gidx = (b0 + b) * H1n + rt * 16 + hl;
        float c = sigm(gf) * g_c1[gidx] + sigm(gi) * tanhf(gg);
        g_c1[gidx] = c;
        h1new[gidx] = sigm(go) * tanhf(c);
    }
}

// ---------------- k_lstm2: grid (4 rowtiles, 16 btiles), 256 thr ------------
#define L2_NC    3
#define L2_SW    0                                  // [3][64][64] f = 49152
#define L2_SXD   49152                              // [192][16] ull = 24576
#define L2_SG    (49152 + 24576)                    // 4608
#define L2_SMEM  (L2_SG + 4608)

__global__ void __launch_bounds__(256) k_lstm2(int p) {
    extern __shared__ __align__(16) char sm[];
    float (*s_w)[64][64] = (float(*)[64][64])(sm + L2_SW);
    ull   (*s_xd)[16]    = (ull(*)[16])(sm + L2_SXD);
    float (*s_g)[18]     = (float(*)[18])(sm + L2_SG);

    const int tid = threadIdx.x;
    const int rt = blockIdx.x, bt = blockIdx.y;
    const int r0 = rt * 64, b0 = bt * 16;
    const float* __restrict__ h1new = g_h1[p ^ 1];
    const float* __restrict__ h2old = g_h2[p];
    float* __restrict__ h2new = g_h2[p ^ 1];

    #pragma unroll
    for (int c = 0; c < L2_NC; c++) {
        #pragma unroll
        for (int i = 0; i < 4; i++) {
            int idx = tid + i * 256;
            int kr = idx >> 4, j4 = idx & 15;
            cpa16(&s_w[c][kr][j4 * 4],
                  &g_w2R[(size_t)(c * 64 + kr) * 256 + r0 + j4 * 4]);
        }
        CP_COMMIT();
    }

    for (int idx = tid; idx < 192 * 16; idx += 256) {
        int k = idx >> 4, b = idx & 15;
        float v = (k < 128) ? h1new[(b0 + b) * H1n + k]
                            : h2old[(b0 + b) * H2n + (k - 128)];
        s_xd[k][b] = dup2(v);
    }

    const int RP = tid >> 3, Bg = tid & 7;
    ull a0 = 0, a1 = 0;

    #pragma unroll 1
    for (int c = 0; c < L2_NC; c++) {
        cp_wait_dyn(L2_NC - 1 - c);
        __syncthreads();
        const float* wb = &s_w[c][0][0];
        const ull*   xb = &s_xd[c * 64][0];
        #pragma unroll
        for (int kk = 0; kk < 64; kk++) {
            ull w = *(const ull*)(wb + kk * 64 + 2 * RP);
            ulonglong2 x2 = *(const ulonglong2*)(xb + kk * 16 + 2 * Bg);
            fma2(a0, w, x2.x);
            fma2(a1, w, x2.y);
        }
    }
    __syncthreads();

    {
        float bl = g_b2R[r0 + 2 * RP], bh = g_b2R[r0 + 2 * RP + 1];
        float v0, v1;
        unpk2(a0, v0, v1);
        s_g[2 * RP][2 * Bg] = v0 + bl; s_g[2 * RP + 1][2 * Bg] = v1 + bh;
        unpk2(a1, v0, v1);
        s_g[2 * RP][2 * Bg + 1] = v0 + bl; s_g[2 * RP + 1][2 * Bg + 1] = v1 + bh;
    }
    __syncthreads();

    {
        int b = tid & 15, hl = tid >> 4;
        float gi = s_g[4 * hl][b],     gf = s_g[4 * hl + 1][b];
        float gg = s_g[4 * hl + 2][b], go = s_g[4 * hl + 3][b];
        int gidx = (b0 + b) * H2n + rt * 16 + hl;
        float c = sigm(gf) * g_c2[gidx] + sigm(gi) * tanhf(gg);
        g_c2[gidx] = c;
        float h = sigm(go) * tanhf(c);
        h2new[gidx] = h;
        g_x[(b0 + b) * 128 + rt * 16 + hl] = h;
    }
}

// ---------------- attention: query + energy + masked softmax + context ------
// grid 256 (one block per b), 256 threads. Also resets g_amax[b].
__global__ void __launch_bounds__(256) k_attn(
    const float* __restrict__ enc_key, const float* __restrict__ enc_val,
    const int* __restrict__ mask, const float* __restrict__ bq)
{
    __shared__ __align__(16) float s_q[64];
    __shared__ float s_h2[64];
    __shared__ float s_qp[4][64];
    __shared__ float s_e[512];
    __shared__ float s_w[512];
    __shared__ float s_red[40];
    __shared__ float s_p[4][64];
    const int b = blockIdx.x, tid = threadIdx.x;
    const int lane = tid & 31, warp = tid >> 5;

    if (tid == 0) g_amax[b] = 0ull;
    if (tid < 64) s_h2[tid] = g_x[b * 128 + tid];
    __syncthreads();

    // query = h2 @ wqT + bq
    {
        int d = tid & 63, kq = tid >> 6;
        float a = 0.f;
        #pragma unroll
        for (int k = kq * 16; k < kq * 16 + 16; k++)
            a += g_wqT[k * 64 + d] * s_h2[k];
        s_qp[kq][d] = a;
    }
    __syncthreads();
    if (tid < 64)
        s_q[tid] = s_qp[0][tid] + s_qp[1][tid] + s_qp[2][tid] + s_qp[3][tid] + bq[tid];
    __syncthreads();

    // energy: thread = (slot, d-quarter); 8 t per thread, 4 LDG.128 per t
    {
        const int slot = tid >> 2, dq = tid & 3;
        const float4* qp = (const float4*)(s_q + dq * 16);
        float4 q0 = qp[0], q1 = qp[1], q2 = qp[2], q3 = qp[3];
        #pragma unroll 4
        for (int i = 0; i < 8; i++) {
            int t = slot + 64 * i;
            const float4* kp = (const float4*)(enc_key + ((size_t)t * Bn + b) * Dn + dq * 16);
            float4 a = kp[0], c = kp[1], d = kp[2], e = kp[3];
            float pp = a.x * q0.x + a.y * q0.y + a.z * q0.z + a.w * q0.w
                     + c.x * q1.x + c.y * q1.y + c.z * q1.z + c.w * q1.w
                     + d.x * q2.x + d.y * q2.y + d.z * q2.z + d.w * q2.w
                     + e.x * q3.x + e.y * q3.y + e.z * q3.z + e.w * q3.w;
            pp += __shfl_xor_sync(0xffffffffu, pp, 1);
            pp += __shfl_xor_sync(0xffffffffu, pp, 2);
            if (dq == 0) s_e[t] = pp;
        }
    }
    __syncthreads();

    float e0 = s_e[tid], e1 = s_e[tid + 256];
    float mx = fmaxf(e0, e1);
    #pragma unroll
    for (int o = 16; o; o >>= 1) mx = fmaxf(mx, __shfl_xor_sync(0xffffffffu, mx, o));
    if (lane == 0) s_red[warp] = mx;
    __syncthreads();
    if (tid == 0) {
        float m = s_red[0];
        #pragma unroll
        for (int i = 1; i < 8; i++) m = fmaxf(m, s_red[i]);
        s_red[32] = m;
    }
    __syncthreads();
    mx = s_red[32];
    int m0 = mask[(size_t)b * Tn + tid], m1 = mask[(size_t)b * Tn + tid + 256];
    float x0 = expf(e0 - mx), x1 = expf(e1 - mx);
    float s = x0 + x1, ws = (m0 ? x0 : 0.f) + (m1 ? x1 : 0.f);
    #pragma unroll
    for (int o = 16; o; o >>= 1) {
        s  += __shfl_xor_sync(0xffffffffu, s,  o);
        ws += __shfl_xor_sync(0xffffffffu, ws, o);
    }
    if (lane == 0) { s_red[warp] = s; s_red[8 + warp] = ws; }
    __syncthreads();
    if (tid == 0) {
        float S = 0.f, W = 0.f;
        #pragma unroll
        for (int i = 0; i < 8; i++) { S += s_red[i]; W += s_red[8 + i]; }
        s_red[33] = 1.0f / (S * fmaxf(W / S, 2e-30f));
    }
    __syncthreads();
    float inv = s_red[33];
    s_w[tid]       = m0 ? x0 * inv : 0.f;
    s_w[tid + 256] = m1 ? x1 * inv : 0.f;
    __syncthreads();

    {
        int d = tid & 63, ch = tid >> 6;
        const float* vb = enc_val + (size_t)b * Dn + d;
        float a0 = 0.f, a1 = 0.f;
        #pragma unroll 4
        for (int t = ch * 128; t < ch * 128 + 128; t += 2) {
            a0 += s_w[t]     * vb[(size_t)t * (Bn * Dn)];
            a1 += s_w[t + 1] * vb[(size_t)(t + 1) * (Bn * Dn)];
        }
        s_p[ch][d] = a0 + a1;
    }
    __syncthreads();
    if (tid < 64) {
        float c = s_p[0][tid] + s_p[1][tid] + s_p[2][tid] + s_p[3][tid];
        g_x[b * 128 + 64 + tid] = c;
    }
}

// ---------------- pred GEMM (full upfront staging) + fused argmax -----------
#define KP_NC    8
#define KP_SWT   0                                  // [8][16][128] f = 65536
#define KP_SXD   65536                              // [32][128] ull  = 32768
#define KP_SMEM  (65536 + 32768)

__global__ void __launch_bounds__(256) k_pred(const float* __restrict__ bp,
                                              float* __restrict__ out, int step) {
    extern __shared__ __align__(16) char sm[];
    float (*s_wt)[16][128] = (float(*)[16][128])(sm + KP_SWT);
    ull   (*s_xd)[128]     = (ull(*)[128])(sm + KP_SXD);
    const int tid = threadIdx.x;
    const int b0 = blockIdx.y * 32;
    const int vt = blockIdx.x;

    // stage ALL 8 weight chunks upfront (one commit group each)
    #pragma unroll
    for (int kc = 0; kc < KP_NC; kc++) {
        #pragma unroll
        for (int i = 0; i < 2; i++) {
            int idx = tid + i * 256;
            int kr = idx >> 5, j4 = idx & 31;
            int v = vt * 128 + j4 * 4;
            if (v + 3 < Vn)
                cpa16(&s_wt[kc][kr][j4 * 4],
                      &g_wpT[(size_t)(kc * 16 + kr) * Vn + v]);
        }
        CP_COMMIT();
    }

    for (int idx = tid; idx < 32 * 128; idx += 256) {
        int b = idx >> 7, k = idx & 127;
        s_xd[b][k] = dup2(g_x[(b0 + b) * 128 + k]);
    }

    const int vq = tid & 31, bq = tid >> 5;
    const int v0 = vt * 128 + vq * 4;
    const bool vok = (v0 + 3) < Vn;

    ull acc0[4] = {}, acc1[4] = {};
    #pragma unroll 1
    for (int kc = 0; kc < KP_NC; kc++) {
        cp_wait_dyn(KP_NC - 1 - kc);
        __syncthreads();
        #pragma unroll
        for (int kr = 0; kr < 16; kr++) {
            int k = kc * 16 + kr;
            ulonglong2 w = *(const ulonglong2*)&s_wt[kc][kr][vq * 4];
            #pragma unroll
            for (int b = 0; b < 4; b++) {
                ull xd = s_xd[bq * 4 + b][k];
                fma2(acc0[b], w.x, xd);
                fma2(acc1[b], w.y, xd);
            }
        }
    }

    float bs0 = 0.f, bs1 = 0.f, bs2 = 0.f, bs3 = 0.f;
    if (vok) {
        float4 b4 = *(const float4*)&bp[v0];
        bs0 = b4.x; bs1 = b4.y; bs2 = b4.z; bs3 = b4.w;
    }

    #pragma unroll
    for (int b = 0; b < 4; b++) {
        int bi = b0 + bq * 4 + b;
        float r0, r1, r2, r3;
        unpk2(acc0[b], r0, r1);
        unpk2(acc1[b], r2, r3);
        r0 += bs0; r1 += bs1; r2 += bs2; r3 += bs3;
        if (vok) {
            __stcs((float4*)(out + (size_t)bi * (ML * Vn) + (size_t)step * Vn + v0),
                   make_float4(r0, r1, r2, r3));
        }
        float best = r0; int bv = v0;
        if (r1 > best) { best = r1; bv = v0 + 1; }
        if (r2 > best) { best = r2; bv = v0 + 2; }
        if (r3 > best) { best = r3; bv = v0 + 3; }
        ull pk = vok ? (((ull)fkey(best) << 32) | (unsigned int)(~bv)) : 0ull;
        #pragma unroll
        for (int o = 16; o; o >>= 1) {
            ull other = __shfl_down_sync(0xffffffffu, pk, o);
            if (other > pk) pk = other;
        }
        if (vq == 0) atomicMax(&g_amax[bi], pk);
    }
}

// ---------------- host ------------------------------------------------------
extern "C" void kernel_launch(void* const* d_in, const int* in_sizes, int n_in,
                              void* d_out, int out_size) {
    const float* enc_key = (const float*)d_in[0];
    const float* enc_val = (const float*)d_in[1];
    const int*   mask    = (const int*)d_in[2];
    const float* emb     = (const float*)d_in[3];
    const float* w_ih1   = (const float*)d_in[4];
    const float* w_hh1   = (const float*)d_in[5];
    const float* b_ih1   = (const float*)d_in[6];
    const float* b_hh1   = (const float*)d_in[7];
    const float* w_ih2   = (const float*)d_in[8];
    const float* w_hh2   = (const float*)d_in[9];
    const float* b_ih2   = (const float*)d_in[10];
    const float* b_hh2   = (const float*)d_in[11];
    const float* wq      = (const float*)d_in[12];
    const float* bq      = (const float*)d_in[13];
    const float* wp      = (const float*)d_in[14];
    const float* bp      = (const float*)d_in[15];
    float* out = (float*)d_out;

    static int s_attr_done = 0;
    if (!s_attr_done) {
        cudaFuncSetAttribute(k_lstm1, cudaFuncAttributeMaxDynamicSharedMemorySize, L1_SMEM);
        cudaFuncSetAttribute(k_lstm2, cudaFuncAttributeMaxDynamicSharedMemorySize, L2_SMEM);
        cudaFuncSetAttribute(k_pred,  cudaFuncAttributeMaxDynamicSharedMemorySize, KP_SMEM);
        s_attr_done = 1;
    }

    k_prep_small<<<640, 256>>>(w_ih1, w_hh1, b_ih1, b_hh1,
                               w_ih2, w_hh2, b_ih2, b_hh2, wq);
    k_prep_wp<<<dim3(313, 4), 256>>>(wp);
    k_init<<<128, 256>>>();
    for (int s = 0; s < ML; s++) {
        int p = s & 1;
        k_lstm1<<<dim3(8, 16), 256, L1_SMEM>>>(emb, p);
        k_lstm2<<<dim3(4, 16), 256, L2_SMEM>>>(p);
        k_attn<<<256, 256>>>(enc_key, enc_val, mask, bq);
        k_pred<<<dim3(79, 8), 256, KP_SMEM>>>(bp, out, s);
    }
}

// round 10
// speedup vs baseline: 1.2556x; 1.2556x over previous
#include <cuda_runtime.h>

#define Bn   256
#define Tn   512
#define Dn   64
#define En   128
#define H1n  128
#define H2n  64
#define Vn   10000
#define ML   30
#define SOS_ 1
#define EOS_ 2

typedef unsigned long long ull;

// ---------------- persistent state + prepped weights (device globals) -------
__device__ float g_h1[2][Bn * H1n];        // ping-pong
__device__ float g_c1[Bn * H1n];
__device__ float g_h2[2][Bn * H2n];        // ping-pong
__device__ float g_c2[Bn * H2n];
__device__ float g_x[Bn * 128];            // [h2(64) | ctx(64)] pred input
__device__ ull   g_amax[Bn];               // packed (fkey(val)<<32 | ~v)

// k-major, gate-interleaved (col = 4*hdim + gate, gates i,f,g,o)
__device__ float g_w1R[320 * 512];         // k<192: wih1, k>=192: whh1
__device__ float g_w2R[192 * 256];         // k<128: wih2, k>=128: whh2
__device__ float g_b1R[512];
__device__ float g_b2R[256];
__device__ float g_wqT[64 * 64];           // [k][d]
__device__ float g_wpT[128 * Vn];          // [k][v]

__device__ __forceinline__ unsigned int fkey(float f) {
    unsigned int u = __float_as_uint(f);
    return (u & 0x80000000u) ? ~u : (u | 0x80000000u);
}
__device__ __forceinline__ float sigm(float x) { return 1.0f / (1.0f + expf(-x)); }

__device__ __forceinline__ void fma2(ull& d, ull a, ull b) {
    asm("fma.rn.f32x2 %0, %1, %2, %0;" : "+l"(d) : "l"(a), "l"(b));
}
__device__ __forceinline__ ull dup2(float x) {
    unsigned int u = __float_as_uint(x); ull r;
    asm("mov.b64 %0, {%1, %1};" : "=l"(r) : "r"(u));
    return r;
}
__device__ __forceinline__ void unpk2(ull a, float& lo, float& hi) {
    unsigned int ul, uh;
    asm("mov.b64 {%0, %1}, %2;" : "=r"(ul), "=r"(uh) : "l"(a));
    lo = __uint_as_float(ul); hi = __uint_as_float(uh);
}
__device__ __forceinline__ void cpa16(void* s, const void* g) {
    unsigned sa = (unsigned)__cvta_generic_to_shared(s);
    asm volatile("cp.async.cg.shared.global [%0], [%1], 16;" :: "r"(sa), "l"(g));
}
#define CP_COMMIT()  asm volatile("cp.async.commit_group;")
#define CP_WAIT0()   asm volatile("cp.async.wait_group 0;")

// ---------------- one-time prep ---------------------------------------------
__global__ void k_prep_small(const float* __restrict__ wih1, const float* __restrict__ whh1,
                             const float* __restrict__ bih1, const float* __restrict__ bhh1,
                             const float* __restrict__ wih2, const float* __restrict__ whh2,
                             const float* __restrict__ bih2, const float* __restrict__ bhh2,
                             const float* __restrict__ wq) {
    int n = blockDim.x * gridDim.x;
    int t0 = blockIdx.x * blockDim.x + threadIdx.x;
    for (int i = t0; i < 320 * 512; i += n) {
        int k = i >> 9, c = i & 511;
        int h = c >> 2, g = c & 3, r = g * 128 + h;
        g_w1R[i] = (k < 192) ? wih1[r * 192 + k] : whh1[r * 128 + (k - 192)];
    }
    for (int i = t0; i < 192 * 256; i += n) {
        int k = i >> 8, c = i & 255;
        int h = c >> 2, g = c & 3, r = g * 64 + h;
        g_w2R[i] = (k < 128) ? wih2[r * 128 + k] : whh2[r * 64 + (k - 128)];
    }
    for (int i = t0; i < 64 * 64; i += n) {
        int k = i >> 6, d = i & 63;
        g_wqT[i] = wq[d * 64 + k];
    }
    for (int c = t0; c < 512; c += n) {
        int h = c >> 2, g = c & 3, r = g * 128 + h;
        g_b1R[c] = bih1[r] + bhh1[r];
    }
    for (int c = t0; c < 256; c += n) {
        int h = c >> 2, g = c & 3, r = g * 64 + h;
        g_b2R[c] = bih2[r] + bhh2[r];
    }
}

// tiled transpose wp[10000][128] -> wpT[128][10000]
__global__ void k_prep_wp(const float* __restrict__ wp) {
    __shared__ float t[32][33];
    int vt = blockIdx.x * 32, kt = blockIdx.y * 32;
    int tx = threadIdx.x & 31, ty = threadIdx.x >> 5;   // 32 x 8
    #pragma unroll
    for (int i = 0; i < 4; i++) {
        int v = vt + ty + i * 8;
        if (v < Vn) t[ty + i * 8][tx] = wp[(size_t)v * 128 + kt + tx];
    }
    __syncthreads();
    int v = vt + tx;
    if (v < Vn) {
        #pragma unroll
        for (int i = 0; i < 4; i++) {
            int k = kt + ty + i * 8;
            g_wpT[(size_t)k * Vn + v] = t[tx][ty + i * 8];
        }
    }
}

__global__ void k_init() {
    int i = blockIdx.x * blockDim.x + threadIdx.x;
    if (i < Bn * H1n) { g_h1[0][i] = 0.f; g_h1[1][i] = 0.f; g_c1[i] = 0.f; }
    if (i < Bn * H2n) { g_h2[0][i] = 0.f; g_h2[1][i] = 0.f; g_c2[i] = 0.f; }
    if (i < Bn * 128) g_x[i] = 0.f;
    if (i < Bn) g_amax[i] = (ull)(~(unsigned int)SOS_);
}

// ---------------- k_lstm1: grid (8 rowtiles, 16 btiles), 512 thr, split-k ---
// 64 rows' (16 hdims) x 16 b; k=320 split 160/160 across thread halves.
#define L1_SW    0                                  // [320][64] f  = 81920
#define L1_SXD   81920                              // [320][18] ull = 46080
#define L1_SP    (81920 + 46080)                    // [256] float4 = 4096
#define L1_SG    (L1_SP + 4096)                     // [64][18] f   = 4608
#define L1_TOK   (L1_SG + 4608)
#define L1_SMEM  (L1_TOK + 64)

__global__ void __launch_bounds__(512) k_lstm1(const float* __restrict__ emb, int p) {
    extern __shared__ __align__(16) char sm[];
    float (*s_w)[64]  = (float(*)[64])(sm + L1_SW);     // [320][64]
    ull   (*s_xd)[18] = (ull(*)[18])(sm + L1_SXD);      // [320][18]
    float4* s_p1      = (float4*)(sm + L1_SP);          // [256]
    float (*s_g)[18]  = (float(*)[18])(sm + L1_SG);
    int*  s_tok       = (int*)(sm + L1_TOK);

    const int tid = threadIdx.x;
    const int rt = blockIdx.x, bt = blockIdx.y;
    const int r0 = rt * 64, b0 = bt * 16;
    const float* __restrict__ h1old = g_h1[p];
    float* __restrict__ h1new = g_h1[p ^ 1];

    // stage ALL weights (320 rows x 16 float4) — 512 threads x 10 cpa16
    #pragma unroll
    for (int i = 0; i < 10; i++) {
        int idx = tid + i * 512;                // 5120 float4 slots
        int kr = idx >> 4, j4 = idx & 15;
        cpa16(&s_w[kr][j4 * 4], &g_w1R[(size_t)kr * 512 + r0 + j4 * 4]);
    }
    CP_COMMIT();

    if (tid < 16) {
        ull a = g_amax[b0 + tid];
        s_tok[tid] = (int)(~(unsigned int)(a & 0xFFFFFFFFull));
    }
    __syncthreads();

    // x fill, b-major for coalesced emb rows: idx -> (b = idx/320, k = rem)
    for (int i = 0; i < 10; i++) {
        int idx = tid + i * 512;                // 5120 elements
        int b = idx / 320, k = idx - b * 320;
        float v;
        if (k < 128) {
            int t = s_tok[b];
            v = (t == EOS_) ? 0.f : emb[(size_t)t * En + k];
        } else if (k < 192) {
            v = g_x[(b0 + b) * 128 + 64 + (k - 128)];
        } else {
            v = h1old[(b0 + b) * H1n + (k - 192)];
        }
        s_xd[k][b] = dup2(v);
    }

    CP_WAIT0();
    __syncthreads();

    const int kg = tid >> 8;                 // k half: 0 or 1
    const int t8 = tid & 255;
    const int RP = t8 >> 3, Bg = t8 & 7;     // rows (2RP,2RP+1) x b (2Bg,2Bg+1)
    ull a0 = 0, a1 = 0;

    {
        const int k0 = kg * 160;
        #pragma unroll 8
        for (int kk = k0; kk < k0 + 160; kk++) {
            ull w = *(const ull*)&s_w[kk][2 * RP];
            ulonglong2 x2 = *(const ulonglong2*)&s_xd[kk][2 * Bg];
            fma2(a0, w, x2.x);
            fma2(a1, w, x2.y);
        }
    }

    // combine halves: kg1 dumps partials, kg0 adds + bias -> s_g
    if (kg == 1) {
        float p00, p01, p10, p11;
        unpk2(a0, p00, p01); unpk2(a1, p10, p11);
        s_p1[t8] = make_float4(p00, p01, p10, p11);
    }
    __syncthreads();
    if (kg == 0) {
        float4 q = s_p1[t8];
        float bl = g_b1R[r0 + 2 * RP], bh = g_b1R[r0 + 2 * RP + 1];
        float v0, v1;
        unpk2(a0, v0, v1);
        s_g[2 * RP][2 * Bg]     = v0 + q.x + bl;
        s_g[2 * RP + 1][2 * Bg] = v1 + q.y + bh;
        unpk2(a1, v0, v1);
        s_g[2 * RP][2 * Bg + 1]     = v0 + q.z + bl;
        s_g[2 * RP + 1][2 * Bg + 1] = v1 + q.w + bh;
    }
    __syncthreads();

    // cell update: 16 hdims x 16 b (first 256 threads)
    if (tid < 256) {
        int b = tid & 15, hl = tid >> 4;
        float gi = s_g[4 * hl][b],     gf = s_g[4 * hl + 1][b];
        float gg = s_g[4 * hl + 2][b], go = s_g[4 * hl + 3][b];
        int gidx = (b0 + b) * H1n + rt * 16 + hl;
        float c = sigm(gf) * g_c1[gidx] + sigm(gi) * tanhf(gg);
        g_c1[gidx] = c;
        h1new[gidx] = sigm(go) * tanhf(c);
    }
}

// ---------------- k_lstm2: grid (4 rowtiles, 16 btiles), 512 thr, split-k ---
#define L2_SW    0                                  // [192][64] f  = 49152
#define L2_SXD   49152                              // [192][18] ull = 27648
#define L2_SP    (49152 + 27648)                    // 4096
#define L2_SG    (L2_SP + 4096)                     // 4608
#define L2_SMEM  (L2_SG + 4608)

__global__ void __launch_bounds__(512) k_lstm2(int p) {
    extern __shared__ __align__(16) char sm[];
    float (*s_w)[64]  = (float(*)[64])(sm + L2_SW);
    ull   (*s_xd)[18] = (ull(*)[18])(sm + L2_SXD);
    float4* s_p1      = (float4*)(sm + L2_SP);
    float (*s_g)[18]  = (float(*)[18])(sm + L2_SG);

    const int tid = threadIdx.x;
    const int rt = blockIdx.x, bt = blockIdx.y;
    const int r0 = rt * 64, b0 = bt * 16;
    const float* __restrict__ h1new = g_h1[p ^ 1];
    const float* __restrict__ h2old = g_h2[p];
    float* __restrict__ h2new = g_h2[p ^ 1];

    #pragma unroll
    for (int i = 0; i < 6; i++) {
        int idx = tid + i * 512;                // 3072 float4 slots
        int kr = idx >> 4, j4 = idx & 15;
        cpa16(&s_w[kr][j4 * 4], &g_w2R[(size_t)kr * 256 + r0 + j4 * 4]);
    }
    CP_COMMIT();

    for (int i = 0; i < 6; i++) {
        int idx = tid + i * 512;                // 3072 elements
        int b = idx / 192, k = idx - b * 192;
        float v = (k < 128) ? h1new[(b0 + b) * H1n + k]
                            : h2old[(b0 + b) * H2n + (k - 128)];
        s_xd[k][b] = dup2(v);
    }

    CP_WAIT0();
    __syncthreads();

    const int kg = tid >> 8;
    const int t8 = tid & 255;
    const int RP = t8 >> 3, Bg = t8 & 7;
    ull a0 = 0, a1 = 0;

    {
        const int k0 = kg * 96;
        #pragma unroll 8
        for (int kk = k0; kk < k0 + 96; kk++) {
            ull w = *(const ull*)&s_w[kk][2 * RP];
            ulonglong2 x2 = *(const ulonglong2*)&s_xd[kk][2 * Bg];
            fma2(a0, w, x2.x);
            fma2(a1, w, x2.y);
        }
    }

    if (kg == 1) {
        float p00, p01, p10, p11;
        unpk2(a0, p00, p01); unpk2(a1, p10, p11);
        s_p1[t8] = make_float4(p00, p01, p10, p11);
    }
    __syncthreads();
    if (kg == 0) {
        float4 q = s_p1[t8];
        float bl = g_b2R[r0 + 2 * RP], bh = g_b2R[r0 + 2 * RP + 1];
        float v0, v1;
        unpk2(a0, v0, v1);
        s_g[2 * RP][2 * Bg]     = v0 + q.x + bl;
        s_g[2 * RP + 1][2 * Bg] = v1 + q.y + bh;
        unpk2(a1, v0, v1);
        s_g[2 * RP][2 * Bg + 1]     = v0 + q.z + bl;
        s_g[2 * RP + 1][2 * Bg + 1] = v1 + q.w + bh;
    }
    __syncthreads();

    if (tid < 256) {
        int b = tid & 15, hl = tid >> 4;
        float gi = s_g[4 * hl][b],     gf = s_g[4 * hl + 1][b];
        float gg = s_g[4 * hl + 2][b], go = s_g[4 * hl + 3][b];
        int gidx = (b0 + b) * H2n + rt * 16 + hl;
        float c = sigm(gf) * g_c2[gidx] + sigm(gi) * tanhf(gg);
        g_c2[gidx] = c;
        float h = sigm(go) * tanhf(c);
        h2new[gidx] = h;
        g_x[(b0 + b) * 128 + rt * 16 + hl] = h;
    }
}

// ---------------- attention: query + energy + masked softmax + context ------
// grid 256 (one block per b), 256 threads. Also resets g_amax[b].
__global__ void __launch_bounds__(256) k_attn(
    const float* __restrict__ enc_key, const float* __restrict__ enc_val,
    const int* __restrict__ mask, const float* __restrict__ bq)
{
    __shared__ __align__(16) float s_q[64];
    __shared__ float s_h2[64];
    __shared__ float s_qp[4][64];
    __shared__ float s_e[512];
    __shared__ float s_w[512];
    __shared__ float s_red[40];
    __shared__ float s_p[4][64];
    const int b = blockIdx.x, tid = threadIdx.x;
    const int lane = tid & 31, warp = tid >> 5;

    if (tid == 0) g_amax[b] = 0ull;
    if (tid < 64) s_h2[tid] = g_x[b * 128 + tid];
    __syncthreads();

    // query = h2 @ wqT + bq
    {
        int d = tid & 63, kq = tid >> 6;
        float a = 0.f;
        #pragma unroll
        for (int k = kq * 16; k < kq * 16 + 16; k++)
            a += g_wqT[k * 64 + d] * s_h2[k];
        s_qp[kq][d] = a;
    }
    __syncthreads();
    if (tid < 64)
        s_q[tid] = s_qp[0][tid] + s_qp[1][tid] + s_qp[2][tid] + s_qp[3][tid] + bq[tid];
    __syncthreads();

    // energy: thread = (slot, d-quarter); 8 t per thread, 4 LDG.128 per t
    {
        const int slot = tid >> 2, dq = tid & 3;
        const float4* qp = (const float4*)(s_q + dq * 16);
        float4 q0 = qp[0], q1 = qp[1], q2 = qp[2], q3 = qp[3];
        #pragma unroll 4
        for (int i = 0; i < 8; i++) {
            int t = slot + 64 * i;
            const float4* kp = (const float4*)(enc_key + ((size_t)t * Bn + b) * Dn + dq * 16);
            float4 a = kp[0], c = kp[1], d = kp[2], e = kp[3];
            float pp = a.x * q0.x + a.y * q0.y + a.z * q0.z + a.w * q0.w
                     + c.x * q1.x + c.y * q1.y + c.z * q1.z + c.w * q1.w
                     + d.x * q2.x + d.y * q2.y + d.z * q2.z + d.w * q2.w
                     + e.x * q3.x + e.y * q3.y + e.z * q3.z + e.w * q3.w;
            pp += __shfl_xor_sync(0xffffffffu, pp, 1);
            pp += __shfl_xor_sync(0xffffffffu, pp, 2);
            if (dq == 0) s_e[t] = pp;
        }
    }
    __syncthreads();

    float e0 = s_e[tid], e1 = s_e[tid + 256];
    float mx = fmaxf(e0, e1);
    #pragma unroll
    for (int o = 16; o; o >>= 1) mx = fmaxf(mx, __shfl_xor_sync(0xffffffffu, mx, o));
    if (lane == 0) s_red[warp] = mx;
    __syncthreads();
    if (tid == 0) {
        float m = s_red[0];
        #pragma unroll
        for (int i = 1; i < 8; i++) m = fmaxf(m, s_red[i]);
        s_red[32] = m;
    }
    __syncthreads();
    mx = s_red[32];
    int m0 = mask[(size_t)b * Tn + tid], m1 = mask[(size_t)b * Tn + tid + 256];
    float x0 = expf(e0 - mx), x1 = expf(e1 - mx);
    float s = x0 + x1, ws = (m0 ? x0 : 0.f) + (m1 ? x1 : 0.f);
    #pragma unroll
    for (int o = 16; o; o >>= 1) {
        s  += __shfl_xor_sync(0xffffffffu, s,  o);
        ws += __shfl_xor_sync(0xffffffffu, ws, o);
    }
    if (lane == 0) { s_red[warp] = s; s_red[8 + warp] = ws; }
    __syncthreads();
    if (tid == 0) {
        float S = 0.f, W = 0.f;
        #pragma unroll
        for (int i = 0; i < 8; i++) { S += s_red[i]; W += s_red[8 + i]; }
        s_red[33] = 1.0f / (S * fmaxf(W / S, 2e-30f));
    }
    __syncthreads();
    float inv = s_red[33];
    s_w[tid]       = m0 ? x0 * inv : 0.f;
    s_w[tid + 256] = m1 ? x1 * inv : 0.f;
    __syncthreads();

    {
        int d = tid & 63, ch = tid >> 6;
        const float* vb = enc_val + (size_t)b * Dn + d;
        float a0 = 0.f, a1 = 0.f;
        #pragma unroll 4
        for (int t = ch * 128; t < ch * 128 + 128; t += 2) {
            a0 += s_w[t]     * vb[(size_t)t * (Bn * Dn)];
            a1 += s_w[t + 1] * vb[(size_t)(t + 1) * (Bn * Dn)];
        }
        s_p[ch][d] = a0 + a1;
    }
    __syncthreads();
    if (tid < 64) {
        float c = s_p[0][tid] + s_p[1][tid] + s_p[2][tid] + s_p[3][tid];
        g_x[b * 128 + 64 + tid] = c;
    }
}

// ---------------- pred GEMM: 512 thr split-k + fused argmax -----------------
#define KP_SWT   0                                  // [128][128] f  = 65536
#define KP_SXD   65536                              // [32][128] ull = 32768
#define KP_SP    (65536 + 32768)                    // [256] 4xfloat4 = 16384
#define KP_SMEM  (KP_SP + 16384)

__global__ void __launch_bounds__(512) k_pred(const float* __restrict__ bp,
                                              float* __restrict__ out, int step) {
    extern __shared__ __align__(16) char sm[];
    float (*s_wt)[128] = (float(*)[128])(sm + KP_SWT);
    ull   (*s_xd)[128] = (ull(*)[128])(sm + KP_SXD);
    float4 (*s_p1)[4]  = (float4(*)[4])(sm + KP_SP);
    const int tid = threadIdx.x;
    const int b0 = blockIdx.y * 32;
    const int vt = blockIdx.x;

    // stage all 128 weight rows (128 x 32 float4 = 4096 slots)
    #pragma unroll
    for (int i = 0; i < 8; i++) {
        int idx = tid + i * 512;
        int kr = idx >> 5, j4 = idx & 31;
        int v = vt * 128 + j4 * 4;
        if (v + 3 < Vn)
            cpa16(&s_wt[kr][j4 * 4], &g_wpT[(size_t)kr * Vn + v]);
    }
    CP_COMMIT();

    for (int i = 0; i < 8; i++) {
        int idx = tid + i * 512;                // 4096 elements
        int b = idx >> 7, k = idx & 127;
        s_xd[b][k] = dup2(g_x[(b0 + b) * 128 + k]);
    }

    CP_WAIT0();
    __syncthreads();

    const int kg = tid >> 8;
    const int t8 = tid & 255;
    const int vq = t8 & 31, bq = t8 >> 5;
    const int v0 = vt * 128 + vq * 4;
    const bool vok = (v0 + 3) < Vn;

    ull acc0[4] = {}, acc1[4] = {};
    {
        const int k0 = kg * 64;
        #pragma unroll 4
        for (int kk = k0; kk < k0 + 64; kk++) {
            ulonglong2 w = *(const ulonglong2*)&s_wt[kk][vq * 4];
            #pragma unroll
            for (int b = 0; b < 4; b++) {
                ull xd = s_xd[bq * 4 + b][kk];
                fma2(acc0[b], w.x, xd);
                fma2(acc1[b], w.y, xd);
            }
        }
    }

    // combine halves
    if (kg == 1) {
        #pragma unroll
        for (int b = 0; b < 4; b++) {
            float p0, p1, p2, p3;
            unpk2(acc0[b], p0, p1);
            unpk2(acc1[b], p2, p3);
            s_p1[t8][b] = make_float4(p0, p1, p2, p3);
        }
    }
    __syncthreads();
    if (kg == 0) {
        float bs0 = 0.f, bs1 = 0.f, bs2 = 0.f, bs3 = 0.f;
        if (vok) {
            float4 b4 = *(const float4*)&bp[v0];
            bs0 = b4.x; bs1 = b4.y; bs2 = b4.z; bs3 = b4.w;
        }
        #pragma unroll
        for (int b = 0; b < 4; b++) {
            int bi = b0 + bq * 4 + b;
            float4 q = s_p1[t8][b];
            float r0, r1, r2, r3;
            unpk2(acc0[b], r0, r1);
            unpk2(acc1[b], r2, r3);
            r0 += q.x + bs0; r1 += q.y + bs1; r2 += q.z + bs2; r3 += q.w + bs3;
            if (vok) {
                __stcs((float4*)(out + (size_t)bi * (ML * Vn) + (size_t)step * Vn + v0),
                       make_float4(r0, r1, r2, r3));
            }
            float best = r0; int bv = v0;
            if (r1 > best) { best = r1; bv = v0 + 1; }
            if (r2 > best) { best = r2; bv = v0 + 2; }
            if (r3 > best) { best = r3; bv = v0 + 3; }
            ull pk = vok ? (((ull)fkey(best) << 32) | (unsigned int)(~bv)) : 0ull;
            #pragma unroll
            for (int o = 16; o; o >>= 1) {
                ull other = __shfl_down_sync(0xffffffffu, pk, o);
                if (other > pk) pk = other;
            }
            if (vq == 0) atomicMax(&g_amax[bi], pk);
        }
    }
}

// ---------------- host ------------------------------------------------------
extern "C" void kernel_launch(void* const* d_in, const int* in_sizes, int n_in,
                              void* d_out, int out_size) {
    const float* enc_key = (const float*)d_in[0];
    const float* enc_val = (const float*)d_in[1];
    const int*   mask    = (const int*)d_in[2];
    const float* emb     = (const float*)d_in[3];
    const float* w_ih1   = (const float*)d_in[4];
    const float* w_hh1   = (const float*)d_in[5];
    const float* b_ih1   = (const float*)d_in[6];
    const float* b_hh1   = (const float*)d_in[7];
    const float* w_ih2   = (const float*)d_in[8];
    const float* w_hh2   = (const float*)d_in[9];
    const float* b_ih2   = (const float*)d_in[10];
    const float* b_hh2   = (const float*)d_in[11];
    const float* wq      = (const float*)d_in[12];
    const float* bq      = (const float*)d_in[13];
    const float* wp      = (const float*)d_in[14];
    const float* bp      = (const float*)d_in[15];
    float* out = (float*)d_out;

    static int s_attr_done = 0;
    if (!s_attr_done) {
        cudaFuncSetAttribute(k_lstm1, cudaFuncAttributeMaxDynamicSharedMemorySize, L1_SMEM);
        cudaFuncSetAttribute(k_lstm2, cudaFuncAttributeMaxDynamicSharedMemorySize, L2_SMEM);
        cudaFuncSetAttribute(k_pred,  cudaFuncAttributeMaxDynamicSharedMemorySize, KP_SMEM);
        s_attr_done = 1;
    }

    k_prep_small<<<640, 256>>>(w_ih1, w_hh1, b_ih1, b_hh1,
                               w_ih2, w_hh2, b_ih2, b_hh2, wq);
    k_prep_wp<<<dim3(313, 4), 256>>>(wp);
    k_init<<<128, 256>>>();
    for (int s = 0; s < ML; s++) {
        int p = s & 1;
        k_lstm1<<<dim3(8, 16), 512, L1_SMEM>>>(emb, p);
        k_lstm2<<<dim3(4, 16), 512, L2_SMEM>>>(p);
        k_attn<<<256, 256>>>(enc_key, enc_val, mask, bq);
        k_pred<<<dim3(79, 8), 512, KP_SMEM>>>(bp, out, s);
    }
}